// round 6
// baseline (speedup 1.0000x reference)
#include <cuda_runtime.h>

// CRF mean log-likelihood, B=1024, S=1024, T=32.
// Inputs (metadata order): emissions f32 [B,S,T], tags i32 [B,S], mask [B,S]
// (dtype probed at runtime: u8 / i32 / f32 / i64 / f64), start f32 [T],
// transitions f32 [T,T], end f32 [T]. Output: 1 float.

#define BATCH 1024
#define SLEN  1024
#define TT    32
#define WPB   4     // warps per block

__device__ double g_contrib[BATCH];
__device__ float  g_cnt[BATCH];

__device__ __forceinline__ float rcpf_(float x) { float r; asm("rcp.approx.f32 %0, %1;" : "=f"(r) : "f"(x)); return r; }
__device__ __forceinline__ unsigned long long pk2(float lo, float hi) {
    unsigned long long r; asm("mov.b64 %0, {%1, %2};" : "=l"(r) : "f"(lo), "f"(hi)); return r;
}
__device__ __forceinline__ void fma2(unsigned long long& d, unsigned long long a, unsigned long long b) {
    asm("fma.rn.f32x2 %0, %1, %2, %0;" : "+l"(d) : "l"(a), "l"(b));
}
__device__ __forceinline__ void upk(unsigned long long v, float& x, float& y) {
    asm("mov.b64 {%0, %1}, %2;" : "=f"(x), "=f"(y) : "l"(v));
}

// Probe mask dtype from its first bytes. mask[0]=mask[1]=true always (len>=256).
//   u8  : b0!=0, b1!=0
//   f32 : b0==0, b3==0x3f          (1.0f = 00 00 80 3f)
//   f64 : b0==0, b3==0             (1.0  = 00*6 f0 3f)
//   i32 : b0!=0, b1==0, b4!=0      (01 00 00 00 01 ...)
//   i64 : b0!=0, b1==0, b4==0      (01 00*7 01 ...)
__device__ __forceinline__ int probe_mask_mode(const void* m) {
    const unsigned char* u = (const unsigned char*)m;
    if (u[0] != 0 && u[1] != 0) return 0;           // u8 / bool
    if (u[0] == 0) return (u[3] != 0) ? 2 : 4;      // f32 : f64
    return (u[4] != 0) ? 1 : 3;                     // i32 : i64
}

__device__ __forceinline__ bool mask_at(const void* m, int mode, size_t k) {
    switch (mode) {
        case 0:  return ((const unsigned char*)m)[k] != 0;
        case 1:  return ((const int*)m)[k] != 0;
        case 2:  return ((const float*)m)[k] != 0.0f;
        case 3:  { const int* p = (const int*)m; return (p[2*k] | p[2*k+1]) != 0; }
        default: { const int* p = (const int*)m; return (p[2*k] | p[2*k+1]) != 0; } // f64: any nonzero bits
    }
}

__global__ void __launch_bounds__(WPB * 32)
crf_forward_kernel(const float* __restrict__ em,
                   const int* __restrict__ tags,
                   const void* __restrict__ maskp,
                   const float* __restrict__ startv,
                   const float* __restrict__ transv,
                   const float* __restrict__ endv)
{
    __shared__ float s_trans[TT * TT];
    __shared__ float s_start[TT];
    __shared__ float s_end[TT];
    __shared__ __align__(16) float s_p[WPB][2][TT];
    __shared__ unsigned s_mb[WPB][SLEN / 32];

    const int tid  = threadIdx.x;
    const int w    = tid >> 5;
    const int lane = tid & 31;
    const int b    = blockIdx.x * WPB + w;

    for (int i = tid; i < TT * TT; i += WPB * 32) s_trans[i] = transv[i];
    if (tid < TT) { s_start[tid] = startv[tid]; s_end[tid] = endv[tid]; }
    __syncthreads();

    // ---- mask scan: head / tail / len + bitmask cache (dtype-probed) ----
    const int mmode = probe_mask_mode(maskp);
    const size_t mbase = (size_t)b * SLEN;
    int head = -1, tail = -1, len = 0;
    #pragma unroll 4
    for (int i = 0; i < SLEN / 32; i++) {
        bool mv = mask_at(maskp, mmode, mbase + i * 32 + lane);
        unsigned bits = __ballot_sync(0xffffffffu, mv);
        if (lane == 0) s_mb[w][i] = bits;
        len += __popc(bits);
        if (bits) {
            if (head < 0) head = i * 32 + (__ffs(bits) - 1);
            tail = i * 32 + 31 - __clz(bits);
        }
    }
    __syncwarp();

    if (len == 0) {
        if (lane == 0) { g_contrib[b] = 0.0; g_cnt[b] = 0.0f; }
        return;
    }

    const float* emb = em + (size_t)b * SLEN * TT;
    const int*   tg  = tags + (size_t)b * SLEN;

    // ---- numerator: gold-path score, accumulated in fp64 ----
    double nsum = 0.0;
    for (int i = 0; i < SLEN / 32; i++) {
        int j = i * 32 + lane;
        if (j > 0 && j != head && ((s_mb[w][i] >> lane) & 1u)) {
            int tj = tg[j], tp = tg[j - 1];
            nsum += (double)s_trans[tp * TT + tj] + (double)emb[j * TT + tj];
        }
    }
    #pragma unroll
    for (int o = 16; o; o >>= 1) nsum += __shfl_xor_sync(0xffffffffu, nsum, o);
    int th = tg[head], tl = tg[tail];
    double num = nsum + (double)s_start[th] + (double)emb[head * TT + th] + (double)s_end[tl];

    // ---- E = exp(trans) column for this lane (precise expf), packed f32x2 ----
    const float L2E = 1.4426950408889634f;
    unsigned long long epk[TT / 2];
    #pragma unroll
    for (int t = 0; t < TT; t += 2) {
        float e0 = expf(s_trans[t * TT + lane]);
        float e1 = expf(s_trans[(t + 1) * TT + lane]);
        epk[t >> 1] = pk2(e0, e1);
    }
    float eend = expf(s_end[lane]);

    float* pr = s_p[w][0];
    float* pw = s_p[w][1];

    // ---- init at head: p = 2^(score2 - score2[0]), C2 carried in fp64 ----
    float s2 = (s_start[lane] + emb[head * TT + lane]) * L2E;
    float c20 = __shfl_sync(0xffffffffu, s2, 0);
    double C2 = (double)c20;
    pr[lane] = exp2f(s2 - c20);
    __syncwarp();

    // ---- forward recursion, 4-step emission prefetch ----
    int j = head + 1;
    float ef0 = emb[min(j + 0, SLEN - 1) * TT + lane];
    float ef1 = emb[min(j + 1, SLEN - 1) * TT + lane];
    float ef2 = emb[min(j + 2, SLEN - 1) * TT + lane];
    float ef3 = emb[min(j + 3, SLEN - 1) * TT + lane];

    while (j <= tail) {
        int jn = j + 4;
        float en0 = emb[min(jn + 0, SLEN - 1) * TT + lane];
        float en1 = emb[min(jn + 1, SLEN - 1) * TT + lane];
        float en2 = emb[min(jn + 2, SLEN - 1) * TT + lane];
        float en3 = emb[min(jn + 3, SLEN - 1) * TT + lane];

        #pragma unroll
        for (int k = 0; k < 4; k++) {
            int jj = j + k;
            float ev = (k == 0) ? ef0 : (k == 1) ? ef1 : (k == 2) ? ef2 : ef3;
            if (jj <= tail && ((s_mb[w][jj >> 5] >> (jj & 31)) & 1u)) {
                float em2v = ev * L2E;
                float em20 = __shfl_sync(0xffffffffu, em2v, 0);
                float eem  = exp2f(em2v - em20);   // off the p-critical chain

                const float4* p4 = (const float4*)pr;
                unsigned long long a0 = 0ull, a1 = 0ull, a2 = 0ull, a3 = 0ull;
                #pragma unroll
                for (int q = 0; q < 8; q++) {
                    float4 v = p4[q];
                    unsigned long long plo = pk2(v.x, v.y);
                    unsigned long long phi = pk2(v.z, v.w);
                    if (q & 1) { fma2(a2, plo, epk[2 * q]); fma2(a3, phi, epk[2 * q + 1]); }
                    else       { fma2(a0, plo, epk[2 * q]); fma2(a1, phi, epk[2 * q + 1]); }
                }
                float x0, y0, x1, y1, x2, y2, x3, y3;
                upk(a0, x0, y0); upk(a1, x1, y1); upk(a2, x2, y2); upk(a3, x3, y3);
                float acc = ((x0 + y0) + (x1 + y1)) + ((x2 + y2) + (x3 + y3));

                float acc0 = __shfl_sync(0xffffffffu, acc, 0);
                float r    = rcpf_(acc0);                      // self-correcting scale
                C2 += (double)log2f(acc0) + (double)em20;      // precise log, fp64 carry
                pw[lane] = acc * eem * r;
                __syncwarp();
                float* t_ = pr; pr = pw; pw = t_;
            }
        }
        ef0 = en0; ef1 = en1; ef2 = en2; ef3 = en3;
        j = jn;
    }

    // ---- denominator + per-batch contribution (fp64) ----
    float v = pr[lane] * eend;
    #pragma unroll
    for (int o = 16; o; o >>= 1) v += __shfl_xor_sync(0xffffffffu, v, o);
    const double LN2 = 0.6931471805599453;
    double denom = (C2 + (double)log2f(v)) * LN2;

    if (lane == 0) {
        g_contrib[b] = (denom - num) / ((double)len + 1e-6);
        g_cnt[b]     = 1.0f;
    }
}

__global__ void crf_reduce_kernel(float* __restrict__ out)
{
    __shared__ double s1[256];
    __shared__ double s2[256];
    int t = threadIdx.x;
    double a = 0.0, c = 0.0;
    for (int i = t; i < BATCH; i += 256) { a += g_contrib[i]; c += (double)g_cnt[i]; }
    s1[t] = a; s2[t] = c;
    __syncthreads();
    #pragma unroll
    for (int k = 128; k; k >>= 1) {
        if (t < k) { s1[t] += s1[t + k]; s2[t] += s2[t + k]; }
        __syncthreads();
    }
    if (t == 0) out[0] = (float)(s1[0] / (s2[0] + 1e-6));
}

extern "C" void kernel_launch(void* const* d_in, const int* in_sizes, int n_in,
                              void* d_out, int out_size)
{
    const float* em    = (const float*)d_in[0];
    const int*   tags  = (const int*)d_in[1];
    const void*  mask  = (const void*)d_in[2];
    const float* st    = (const float*)d_in[3];
    const float* tr    = (const float*)d_in[4];
    const float* en    = (const float*)d_in[5];

    crf_forward_kernel<<<BATCH / WPB, WPB * 32>>>(em, tags, mask, st, tr, en);
    crf_reduce_kernel<<<1, 256>>>((float*)d_out);
}

// round 7
// speedup vs baseline: 1.3740x; 1.3740x over previous
#include <cuda_runtime.h>

// CRF mean log-likelihood, B=1024, S=1024, T=32.
// Inputs (metadata order): emissions f32 [B,S,T], tags i32 [B,S], mask [B,S]
// (dtype probed at runtime), start f32 [T], transitions f32 [T,T], end f32 [T].
// Output: 1 float.

#define BATCH 1024
#define SLEN  1024
#define TT    32
#define WPB   7
#define NBLK  ((BATCH + WPB - 1) / WPB)   // 147 blocks -> single wave on 148 SMs

__device__ double   g_contrib[BATCH];
__device__ double   g_cnt[BATCH];
__device__ unsigned g_sem = 0;

__device__ __forceinline__ float ex2f_(float x) { float r; asm("ex2.approx.f32 %0, %1;" : "=f"(r) : "f"(x)); return r; }
__device__ __forceinline__ unsigned long long pk2(float lo, float hi) {
    unsigned long long r; asm("mov.b64 %0, {%1, %2};" : "=l"(r) : "f"(lo), "f"(hi)); return r;
}
__device__ __forceinline__ void fma2(unsigned long long& d, unsigned long long a, unsigned long long b) {
    asm("fma.rn.f32x2 %0, %1, %2, %0;" : "+l"(d) : "l"(a), "l"(b));
}
__device__ __forceinline__ void add2(unsigned long long& d, unsigned long long a, unsigned long long b) {
    asm("add.rn.f32x2 %0, %1, %2;" : "=l"(d) : "l"(a), "l"(b));
}
__device__ __forceinline__ void upk(unsigned long long v, float& x, float& y) {
    asm("mov.b64 {%0, %1}, %2;" : "=f"(x), "=f"(y) : "l"(v));
}

// Probe mask dtype from its first bytes (mask[0]=mask[1]=true since len>=256).
__device__ __forceinline__ int probe_mask_mode(const void* m) {
    const unsigned char* u = (const unsigned char*)m;
    if (u[0] != 0 && u[1] != 0) return 0;           // u8 / bool
    if (u[0] == 0) return (u[3] != 0) ? 2 : 4;      // f32 : f64
    return (u[4] != 0) ? 1 : 3;                     // i32 : i64
}
__device__ __forceinline__ bool mask_at(const void* m, int mode, size_t k) {
    switch (mode) {
        case 0:  return ((const unsigned char*)m)[k] != 0;
        case 1:  return ((const int*)m)[k] != 0;
        case 2:  return ((const float*)m)[k] != 0.0f;
        default: { const int* p = (const int*)m; return (p[2*k] | p[2*k+1]) != 0; } // 64-bit
    }
}

__global__ void __launch_bounds__(WPB * 32)
crf_fused_kernel(const float* __restrict__ em,
                 const int* __restrict__ tags,
                 const void* __restrict__ maskp,
                 const float* __restrict__ startv,
                 const float* __restrict__ transv,
                 const float* __restrict__ endv,
                 float* __restrict__ out)
{
    __shared__ float s_trans[TT * TT];
    __shared__ float s_start[TT];
    __shared__ float s_end[TT];
    __shared__ __align__(16) float s_p[WPB][2][TT];
    __shared__ unsigned s_mb[WPB][SLEN / 32];
    __shared__ bool   s_last;
    __shared__ double s_r1[WPB], s_r2[WPB];

    const int tid  = threadIdx.x;
    const int w    = tid >> 5;
    const int lane = tid & 31;
    const int b    = blockIdx.x * WPB + w;

    for (int i = tid; i < TT * TT; i += WPB * 32) s_trans[i] = transv[i];
    if (tid < TT) { s_start[tid] = startv[tid]; s_end[tid] = endv[tid]; }
    __syncthreads();

    if (b < BATCH) {
        // ---- mask scan: head / tail / len + bitmask cache ----
        const int mmode = probe_mask_mode(maskp);
        const size_t mbase = (size_t)b * SLEN;
        int head = -1, tail = -1, len = 0;
        #pragma unroll 4
        for (int i = 0; i < SLEN / 32; i++) {
            bool mv = mask_at(maskp, mmode, mbase + i * 32 + lane);
            unsigned bits = __ballot_sync(0xffffffffu, mv);
            if (lane == 0) s_mb[w][i] = bits;
            len += __popc(bits);
            if (bits) {
                if (head < 0) head = i * 32 + (__ffs(bits) - 1);
                tail = i * 32 + 31 - __clz(bits);
            }
        }
        __syncwarp();

        if (len == 0) {
            if (lane == 0) { g_contrib[b] = 0.0; g_cnt[b] = 0.0; }
        } else {
            const float* emb = em + (size_t)b * SLEN * TT;
            const int*   tg  = tags + (size_t)b * SLEN;

            // ---- numerator: gold-path score, fp64 ----
            double nsum = 0.0;
            for (int i = 0; i < SLEN / 32; i++) {
                int j = i * 32 + lane;
                if (j > 0 && j != head && ((s_mb[w][i] >> lane) & 1u)) {
                    int tj = tg[j], tp = tg[j - 1];
                    nsum += (double)s_trans[tp * TT + tj] + (double)emb[j * TT + tj];
                }
            }
            #pragma unroll
            for (int o = 16; o; o >>= 1) nsum += __shfl_xor_sync(0xffffffffu, nsum, o);
            int th = tg[head], tl = tg[tail];
            double num = nsum + (double)s_start[th] + (double)emb[head * TT + th] + (double)s_end[tl];

            // ---- E = exp(trans) column for this lane, packed f32x2 (one-time, precise) ----
            const float L2E = 1.4426950408889634f;
            unsigned long long epk[TT / 2];
            #pragma unroll
            for (int t = 0; t < TT; t += 2) {
                epk[t >> 1] = pk2(expf(s_trans[t * TT + lane]),
                                  expf(s_trans[(t + 1) * TT + lane]));
            }
            float eend = expf(s_end[lane]);

            float* pr = s_p[w][0];
            float* pw = s_p[w][1];

            // ---- init at head (precise, one-time) ----
            float s2  = (s_start[lane] + emb[head * TT + lane]) * L2E;
            float c20 = __shfl_sync(0xffffffffu, s2, 0);
            pr[lane] = exp2f(s2 - c20);
            __syncwarp();

            // ---- forward recursion: lazy power-of-2 scaling, eem pipelined 1 group ahead ----
            int j = head + 1;
            float efA[4], efB[4], eA[4], eB[4], m2A[4], m2B[4];
            #pragma unroll
            for (int k = 0; k < 4; k++) efA[k] = emb[min(j + k,     SLEN - 1) * TT + lane];
            #pragma unroll
            for (int k = 0; k < 4; k++) efB[k] = emb[min(j + 4 + k, SLEN - 1) * TT + lane];
            #pragma unroll
            for (int k = 0; k < 4; k++) {
                float t = efA[k] * L2E;
                float t0 = __shfl_sync(0xffffffffu, t, 0);
                eA[k] = ex2f_(t - t0); m2A[k] = t0;
            }

            float  sc    = 1.0f;
            float  escv  = eA[0];      // eem * sc for the upcoming step
            float  m20c  = m2A[0];
            int    Kacc  = 0;          // exact integer log2-scale accumulator
            double EMsum = 0.0;        // sum of em20 (log2 units), off critical path

            while (j <= tail) {
                float efN[4];
                #pragma unroll
                for (int k = 0; k < 4; k++) efN[k] = emb[min(j + 8 + k, SLEN - 1) * TT + lane];
                #pragma unroll
                for (int k = 0; k < 4; k++) {
                    float t = efB[k] * L2E;
                    float t0 = __shfl_sync(0xffffffffu, t, 0);
                    eB[k] = ex2f_(t - t0); m2B[k] = t0;
                }

                #pragma unroll
                for (int k = 0; k < 4; k++) {
                    int jj = j + k;
                    if (jj <= tail && ((s_mb[w][jj >> 5] >> (jj & 31)) & 1u)) {
                        const ulonglong2* pv = (const ulonglong2*)pr;
                        ulonglong2 v0 = pv[0], v1 = pv[1], v2 = pv[2], v3 = pv[3];
                        ulonglong2 v4 = pv[4], v5 = pv[5], v6 = pv[6], v7 = pv[7];
                        unsigned long long a0 = 0ull, a1 = 0ull, a2 = 0ull, a3 = 0ull;
                        fma2(a0, v0.x, epk[0]);  fma2(a1, v0.y, epk[1]);
                        fma2(a2, v1.x, epk[2]);  fma2(a3, v1.y, epk[3]);
                        fma2(a0, v2.x, epk[4]);  fma2(a1, v2.y, epk[5]);
                        fma2(a2, v3.x, epk[6]);  fma2(a3, v3.y, epk[7]);
                        fma2(a0, v4.x, epk[8]);  fma2(a1, v4.y, epk[9]);
                        fma2(a2, v5.x, epk[10]); fma2(a3, v5.y, epk[11]);
                        fma2(a0, v6.x, epk[12]); fma2(a1, v6.y, epk[13]);
                        fma2(a2, v7.x, epk[14]); fma2(a3, v7.y, epk[15]);
                        add2(a0, a0, a1); add2(a2, a2, a3); add2(a0, a0, a2);
                        float x, y; upk(a0, x, y);
                        float acc  = x + y;
                        float pnew = acc * escv;      // eem * pending power-of-2 scale
                        pw[lane] = pnew;

                        // off-critical bookkeeping: next power-of-2 scale from p0's exponent
                        float p0n = __shfl_sync(0xffffffffu, pnew, 0);
                        int   e   = __float_as_int(p0n) >> 23;
                        Kacc += e - 127;
                        sc    = __int_as_float((254 - e) << 23);   // 2^(127-e)
                        EMsum += (double)m20c;

                        __syncwarp();
                        float* t_ = pr; pr = pw; pw = t_;
                    }
                    escv = ((k < 3) ? eA[k + 1] : eB[0]) * sc;
                    m20c = (k < 3) ? m2A[k + 1] : m2B[0];
                }
                #pragma unroll
                for (int k = 0; k < 4; k++) { eA[k] = eB[k]; m2A[k] = m2B[k]; efB[k] = efN[k]; }
                j += 4;
            }

            // ---- denominator: single precise log at the end ----
            float vv = pr[lane] * eend;
            #pragma unroll
            for (int o = 16; o; o >>= 1) vv += __shfl_xor_sync(0xffffffffu, vv, o);
            const double LN2 = 0.6931471805599453;
            double denom = ((double)c20 + EMsum + (double)Kacc + (double)log2f(vv)) * LN2;

            if (lane == 0) {
                g_contrib[b] = (denom - num) / ((double)len + 1e-6);
                g_cnt[b]     = 1.0;
            }
        }
    }

    // ---- last-block-done fused reduction (deterministic fixed order) ----
    __syncthreads();
    if (tid == 0) {
        __threadfence();
        s_last = (atomicAdd(&g_sem, 1u) == (unsigned)(gridDim.x - 1));
    }
    __syncthreads();
    if (s_last) {
        __threadfence();
        double a = 0.0, c = 0.0;
        for (int i = tid; i < BATCH; i += WPB * 32) { a += g_contrib[i]; c += g_cnt[i]; }
        #pragma unroll
        for (int o = 16; o; o >>= 1) {
            a += __shfl_xor_sync(0xffffffffu, a, o);
            c += __shfl_xor_sync(0xffffffffu, c, o);
        }
        if (lane == 0) { s_r1[w] = a; s_r2[w] = c; }
        __syncthreads();
        if (tid == 0) {
            double A = 0.0, C = 0.0;
            for (int i = 0; i < WPB; i++) { A += s_r1[i]; C += s_r2[i]; }
            out[0] = (float)(A / (C + 1e-6));
            g_sem = 0;   // re-arm for next graph replay
        }
    }
}

extern "C" void kernel_launch(void* const* d_in, const int* in_sizes, int n_in,
                              void* d_out, int out_size)
{
    const float* em    = (const float*)d_in[0];
    const int*   tags  = (const int*)d_in[1];
    const void*  mask  = (const void*)d_in[2];
    const float* st    = (const float*)d_in[3];
    const float* tr    = (const float*)d_in[4];
    const float* en    = (const float*)d_in[5];

    crf_fused_kernel<<<NBLK, WPB * 32>>>(em, tags, mask, st, tr, en, (float*)d_out);
}

// round 10
// speedup vs baseline: 2.9387x; 2.1387x over previous
#include <cuda_runtime.h>

// CRF mean log-likelihood, B=1024, S=1024, T=32.
// Inputs (metadata order): emissions f32 [B,S,T], tags i32 [B,S], mask [B,S]
// (dtype probed at runtime), start f32 [T], transitions f32 [T,T], end f32 [T].
// Output: 1 float.
//
// Strategy: per batch, TWO warps — forward chain head->mid and backward chain
// tail->mid (beta recursion, transposed E). Z = sum_t alpha_mid[t]*beta_mid[t].
// Scaled (exp-domain) recursion with lazy power-of-2 normalization; branchless
// mainloop (mask is a contiguous prefix).

#define BATCH   1024
#define SLEN    1024
#define TT      32
#define BPB     7                       // batches per block
#define NWARP   (BPB * 2)               // 14 warps
#define THREADS (NWARP * 32)            // 448
#define NBLK    ((BATCH + BPB - 1) / BPB)  // 147 blocks -> one wave

__device__ double   g_contrib[BATCH];
__device__ double   g_cnt[BATCH];
__device__ unsigned g_sem = 0;

__device__ __forceinline__ float ex2f_(float x) { float r; asm("ex2.approx.f32 %0, %1;" : "=f"(r) : "f"(x)); return r; }
__device__ __forceinline__ unsigned long long pk2(float lo, float hi) {
    unsigned long long r; asm("mov.b64 %0, {%1, %2};" : "=l"(r) : "f"(lo), "f"(hi)); return r;
}
__device__ __forceinline__ void fma2(unsigned long long& d, unsigned long long a, unsigned long long b) {
    asm("fma.rn.f32x2 %0, %1, %2, %0;" : "+l"(d) : "l"(a), "l"(b));
}
__device__ __forceinline__ void add2(unsigned long long& d, unsigned long long a, unsigned long long b) {
    asm("add.rn.f32x2 %0, %1, %2;" : "=l"(d) : "l"(a), "l"(b));
}
__device__ __forceinline__ void upk(unsigned long long v, float& x, float& y) {
    asm("mov.b64 {%0, %1}, %2;" : "=f"(x), "=f"(y) : "l"(v));
}

// Probe mask dtype from its first bytes (mask[0]=mask[1]=true since len>=256).
__device__ __forceinline__ int probe_mask_mode(const void* m) {
    const unsigned char* u = (const unsigned char*)m;
    if (u[0] != 0 && u[1] != 0) return 0;           // u8 / bool
    if (u[0] == 0) return (u[3] != 0) ? 2 : 4;      // f32 : f64
    return (u[4] != 0) ? 1 : 3;                     // i32 : i64
}
__device__ __forceinline__ bool mask_at(const void* m, int mode, size_t k) {
    switch (mode) {
        case 0:  return ((const unsigned char*)m)[k] != 0;
        case 1:  return ((const int*)m)[k] != 0;
        case 2:  return ((const float*)m)[k] != 0.0f;
        default: { const int* p = (const int*)m; return (p[2*k] | p[2*k+1]) != 0; } // 64-bit
    }
}

// acc[lane] = sum over 32 entries of (vec pairs) * (epk pairs), f32x2 packed.
__device__ __forceinline__ float dot16(const float* __restrict__ pr,
                                       const unsigned long long* __restrict__ epk) {
    const ulonglong2* pv = (const ulonglong2*)pr;
    ulonglong2 v0 = pv[0], v1 = pv[1], v2 = pv[2], v3 = pv[3];
    ulonglong2 v4 = pv[4], v5 = pv[5], v6 = pv[6], v7 = pv[7];
    unsigned long long a0 = 0ull, a1 = 0ull, a2 = 0ull, a3 = 0ull;
    fma2(a0, v0.x, epk[0]);  fma2(a1, v0.y, epk[1]);
    fma2(a2, v1.x, epk[2]);  fma2(a3, v1.y, epk[3]);
    fma2(a0, v2.x, epk[4]);  fma2(a1, v2.y, epk[5]);
    fma2(a2, v3.x, epk[6]);  fma2(a3, v3.y, epk[7]);
    fma2(a0, v4.x, epk[8]);  fma2(a1, v4.y, epk[9]);
    fma2(a2, v5.x, epk[10]); fma2(a3, v5.y, epk[11]);
    fma2(a0, v6.x, epk[12]); fma2(a1, v6.y, epk[13]);
    fma2(a2, v7.x, epk[14]); fma2(a3, v7.y, epk[15]);
    add2(a0, a0, a1); add2(a2, a2, a3); add2(a0, a0, a2);
    float x, y; upk(a0, x, y);
    return x + y;
}

__global__ void __launch_bounds__(THREADS)
crf_fused_kernel(const float* __restrict__ em,
                 const int* __restrict__ tags,
                 const void* __restrict__ maskp,
                 const float* __restrict__ startv,
                 const float* __restrict__ transv,
                 const float* __restrict__ endv,
                 float* __restrict__ out)
{
    __shared__ float s_trans[TT * TT];
    __shared__ float s_start[TT];
    __shared__ float s_end[TT];
    __shared__ __align__(16) float s_pf[BPB][2][TT];   // forward double buffers
    __shared__ __align__(16) float s_pb[BPB][2][TT];   // backward double buffers
    __shared__ __align__(16) float s_bm[BPB][TT];      // B_mid (raw scaled)
    __shared__ double s_nb[BPB];                       // backward numerator partial
    __shared__ double s_cb[BPB];                       // backward log2 constant (EMsumB + Kb)
    __shared__ double s_r1[NWARP], s_r2[NWARP];
    __shared__ bool   s_last;

    const int  tid  = threadIdx.x;
    const int  w    = tid >> 5;
    const int  lane = tid & 31;
    const bool isF  = (w < BPB);
    const int  slot = isF ? w : (w - BPB);
    const int  b    = blockIdx.x * BPB + slot;

    for (int i = tid; i < TT * TT; i += THREADS) s_trans[i] = transv[i];
    if (tid < TT) { s_start[tid] = startv[tid]; s_end[tid] = endv[tid]; }
    __syncthreads();

    const float L2E = 1.4426950408889634f;

    int head = 0, tail = -1, len = 0;
    if (b < BATCH) {
        // mask scan (contiguous prefix; compute head/tail/len generically)
        const int mmode = probe_mask_mode(maskp);
        const size_t mbase = (size_t)b * SLEN;
        int h = -1;
        #pragma unroll 4
        for (int i = 0; i < SLEN / 32; i++) {
            bool mv = mask_at(maskp, mmode, mbase + i * 32 + lane);
            unsigned bits = __ballot_sync(0xffffffffu, mv);
            len += __popc(bits);
            if (bits) {
                if (h < 0) h = i * 32 + (__ffs(bits) - 1);
                tail = i * 32 + 31 - __clz(bits);
            }
        }
        head = (h < 0) ? 0 : h;
    }

    if (b < BATCH && len > 0) {
        const float* emb = em + (size_t)b * SLEN * TT;
        const int*   tg  = tags + (size_t)b * SLEN;
        const int    mid = (head + tail) >> 1;

        if (isF) {
            // ================= FORWARD WARP =================
            // numerator half: j in (head, mid]
            double nsum = 0.0;
            #pragma unroll 4
            for (int j = head + 1 + lane; j <= mid; j += 32) {
                int tj = tg[j], tp = tg[j - 1];
                nsum += (double)s_trans[tp * TT + tj] + (double)emb[j * TT + tj];
            }
            #pragma unroll
            for (int o = 16; o; o >>= 1) nsum += __shfl_xor_sync(0xffffffffu, nsum, o);
            int th = tg[head], tl = tg[tail];
            nsum += (double)s_start[th] + (double)emb[head * TT + th] + (double)s_end[tl];

            // E columns for this lane, packed f32x2 (precise, one-time)
            unsigned long long epk[TT / 2];
            #pragma unroll
            for (int t = 0; t < TT; t += 2)
                epk[t >> 1] = pk2(expf(s_trans[t * TT + lane]),
                                  expf(s_trans[(t + 1) * TT + lane]));

            float* pr = s_pf[slot][0];
            float* pw = s_pf[slot][1];

            float s2  = (s_start[lane] + emb[head * TT + lane]) * L2E;
            float c20 = __shfl_sync(0xffffffffu, s2, 0);
            pr[lane] = exp2f(s2 - c20);
            __syncwarp();

            const int nst = mid - head;
            double EMs = 0.0; int Kacc = 0, pend = 0; float sc = 1.0f;
            int j = head + 1;

            float efA[4], efB[4], eA[4], mA[4];
            #pragma unroll
            for (int k = 0; k < 4; k++) efA[k] = emb[min(j + k,     SLEN - 1) * TT + lane];
            #pragma unroll
            for (int k = 0; k < 4; k++) efB[k] = emb[min(j + 4 + k, SLEN - 1) * TT + lane];
            #pragma unroll
            for (int k = 0; k < 4; k++) {
                float t = efA[k] * L2E;
                float t0 = __shfl_sync(0xffffffffu, t, 0);
                eA[k] = ex2f_(t - t0); mA[k] = t0;
            }

            int done = 0;
            while (done + 4 <= nst) {
                float efN[4], eB[4], mB[4];
                #pragma unroll
                for (int k = 0; k < 4; k++) efN[k] = emb[min(j + 8 + k, SLEN - 1) * TT + lane];
                #pragma unroll
                for (int k = 0; k < 4; k++) {
                    float t = efB[k] * L2E;
                    float t0 = __shfl_sync(0xffffffffu, t, 0);
                    eB[k] = ex2f_(t - t0); mB[k] = t0;
                }
                #pragma unroll
                for (int k = 0; k < 4; k++) {
                    float acc  = dot16(pr, epk);
                    float pnew = acc * (eA[k] * sc);
                    pw[lane] = pnew;
                    float p0n = __shfl_sync(0xffffffffu, pnew, 0);
                    int e = __float_as_int(p0n) >> 23;
                    Kacc += pend; pend = e - 127;
                    sc = __int_as_float((254 - e) << 23);
                    EMs += (double)mA[k];
                    __syncwarp();
                    float* t_ = pr; pr = pw; pw = t_;
                }
                #pragma unroll
                for (int k = 0; k < 4; k++) { eA[k] = eB[k]; mA[k] = mB[k]; efB[k] = efN[k]; }
                j += 4; done += 4;
            }
            for (int k = 0; done < nst; k++, done++) {
                float acc  = dot16(pr, epk);
                float pnew = acc * (eA[k] * sc);
                pw[lane] = pnew;
                float p0n = __shfl_sync(0xffffffffu, pnew, 0);
                int e = __float_as_int(p0n) >> 23;
                Kacc += pend; pend = e - 127;
                sc = __int_as_float((254 - e) << 23);
                EMs += (double)mA[k];
                __syncwarp();
                float* t_ = pr; pr = pw; pw = t_;
            }
            // NOTE: last pend intentionally dropped (its sc was never applied)

            __syncthreads();   // backward results ready

            // combine: Z = sum_t alpha_mid[t] * B_mid[t]
            float vv = pr[lane] * s_bm[slot][lane];
            #pragma unroll
            for (int o = 16; o; o >>= 1) vv += __shfl_xor_sync(0xffffffffu, vv, o);
            const double LN2 = 0.6931471805599453;
            double denom = ((double)c20 + EMs + (double)Kacc + s_cb[slot] + (double)log2f(vv)) * LN2;
            double num   = nsum + s_nb[slot];

            if (lane == 0) {
                g_contrib[b] = (denom - num) / ((double)len + 1e-6);
                g_cnt[b]     = 1.0;
            }
        } else {
            // ================= BACKWARD WARP =================
            // numerator half: j in (mid, tail]
            double nsum = 0.0;
            #pragma unroll 4
            for (int j = mid + 1 + lane; j <= tail; j += 32) {
                int tj = tg[j], tp = tg[j - 1];
                nsum += (double)s_trans[tp * TT + tj] + (double)emb[j * TT + tj];
            }
            #pragma unroll
            for (int o = 16; o; o >>= 1) nsum += __shfl_xor_sync(0xffffffffu, nsum, o);
            if (lane == 0) s_nb[slot] = nsum;

            // E rows for this lane (transposed), packed f32x2
            unsigned long long epk[TT / 2];
            #pragma unroll
            for (int t = 0; t < TT; t += 2)
                epk[t >> 1] = pk2(expf(s_trans[lane * TT + t]),
                                  expf(s_trans[lane * TT + t + 1]));

            float* qr = s_pb[slot][0];
            float* qw = s_pb[slot][1];

            // init: v_tail = eem_tail * eend   (precise one-time)
            float em2t = emb[tail * TT + lane] * L2E;
            float t0i  = __shfl_sync(0xffffffffu, em2t, 0);
            float vin  = exp2f(em2t - t0i) * expf(s_end[lane]);
            qr[lane] = vin;
            double EMs = (double)t0i;
            float v0n = __shfl_sync(0xffffffffu, vin, 0);
            int   e0  = __float_as_int(v0n) >> 23;
            int Kacc = 0, pend = e0 - 127;
            float sc = __int_as_float((254 - e0) << 23);
            __syncwarp();

            const int nreg = tail - mid - 1;   // eem-consuming dots
            int j = tail - 1;                  // first eem index (descending)

            float efA[4], efB[4], eA[4], mA[4];
            #pragma unroll
            for (int k = 0; k < 4; k++) efA[k] = emb[max(j - k,     0) * TT + lane];
            #pragma unroll
            for (int k = 0; k < 4; k++) efB[k] = emb[max(j - 4 - k, 0) * TT + lane];
            #pragma unroll
            for (int k = 0; k < 4; k++) {
                float t = efA[k] * L2E;
                float t0 = __shfl_sync(0xffffffffu, t, 0);
                eA[k] = ex2f_(t - t0); mA[k] = t0;
            }

            int done = 0;
            while (done + 4 <= nreg) {
                float efN[4], eB[4], mB[4];
                #pragma unroll
                for (int k = 0; k < 4; k++) efN[k] = emb[max(j - 8 - k, 0) * TT + lane];
                #pragma unroll
                for (int k = 0; k < 4; k++) {
                    float t = efB[k] * L2E;
                    float t0 = __shfl_sync(0xffffffffu, t, 0);
                    eB[k] = ex2f_(t - t0); mB[k] = t0;
                }
                #pragma unroll
                for (int k = 0; k < 4; k++) {
                    float acc  = dot16(qr, epk);
                    float vnew = acc * (eA[k] * sc);
                    qw[lane] = vnew;
                    float q0n = __shfl_sync(0xffffffffu, vnew, 0);
                    int e = __float_as_int(q0n) >> 23;
                    Kacc += pend; pend = e - 127;
                    sc = __int_as_float((254 - e) << 23);
                    EMs += (double)mA[k];
                    __syncwarp();
                    float* t_ = qr; qr = qw; qw = t_;
                }
                #pragma unroll
                for (int k = 0; k < 4; k++) { eA[k] = eB[k]; mA[k] = mB[k]; efB[k] = efN[k]; }
                j -= 4; done += 4;
            }
            for (int k = 0; done < nreg; k++, done++) {
                float acc  = dot16(qr, epk);
                float vnew = acc * (eA[k] * sc);
                qw[lane] = vnew;
                float q0n = __shfl_sync(0xffffffffu, vnew, 0);
                int e = __float_as_int(q0n) >> 23;
                Kacc += pend; pend = e - 127;
                sc = __int_as_float((254 - e) << 23);
                EMs += (double)mA[k];
                __syncwarp();
                float* t_ = qr; qr = qw; qw = t_;
            }

            // final dot (no emission): B_mid = E * v_{mid+1}, apply pending sc
            float accF = dot16(qr, epk);
            float bm   = accF * sc;
            Kacc += pend;
            s_bm[slot][lane] = bm;
            if (lane == 0) s_cb[slot] = EMs + (double)Kacc;

            __syncthreads();   // matches forward's barrier
        }
    } else {
        if (b < BATCH && isF && lane == 0) { g_contrib[b] = 0.0; g_cnt[b] = 0.0; }
        __syncthreads();       // all threads join the block barrier
    }

    // ---- last-block-done fused reduction (deterministic fixed order) ----
    __syncthreads();
    if (tid == 0) {
        __threadfence();
        s_last = (atomicAdd(&g_sem, 1u) == (unsigned)(gridDim.x - 1));
    }
    __syncthreads();
    if (s_last) {
        __threadfence();
        double a = 0.0, c = 0.0;
        for (int i = tid; i < BATCH; i += THREADS) { a += g_contrib[i]; c += g_cnt[i]; }
        #pragma unroll
        for (int o = 16; o; o >>= 1) {
            a += __shfl_xor_sync(0xffffffffu, a, o);
            c += __shfl_xor_sync(0xffffffffu, c, o);
        }
        if (lane == 0) { s_r1[w] = a; s_r2[w] = c; }
        __syncthreads();
        if (tid == 0) {
            double A = 0.0, C = 0.0;
            for (int i = 0; i < NWARP; i++) { A += s_r1[i]; C += s_r2[i]; }
            out[0] = (float)(A / (C + 1e-6));
            g_sem = 0;   // re-arm for next graph replay
        }
    }
}

extern "C" void kernel_launch(void* const* d_in, const int* in_sizes, int n_in,
                              void* d_out, int out_size)
{
    const float* em    = (const float*)d_in[0];
    const int*   tags  = (const int*)d_in[1];
    const void*  mask  = (const void*)d_in[2];
    const float* st    = (const float*)d_in[3];
    const float* tr    = (const float*)d_in[4];
    const float* en    = (const float*)d_in[5];

    crf_fused_kernel<<<NBLK, THREADS>>>(em, tags, mask, st, tr, en, (float*)d_out);
}

// round 11
// speedup vs baseline: 3.9976x; 1.3603x over previous
#include <cuda_runtime.h>

// CRF mean log-likelihood, B=1024, S=1024, T=32.
// Inputs (metadata order): emissions f32 [B,S,T], tags i32 [B,S], mask [B,S]
// (dtype probed at runtime), start f32 [T], transitions f32 [T,T], end f32 [T].
// Output: 1 float.
//
// Per batch: forward warp (head->mid) + backward warp (tail->mid), register-
// resident scaled recursion. Matvec: 4-way t-quarter split per lane, 8 shfl.idx
// gathers + 16 packed f32x2 FMAs + 3-shfl butterfly combine. No smem in the
// mainloop. Lazy exact power-of-2 normalization (pend/Kacc).

#define BATCH   1024
#define SLEN    1024
#define TT      32
#define BPB     7
#define NWARP   (BPB * 2)
#define THREADS (NWARP * 32)
#define NBLK    ((BATCH + BPB - 1) / BPB)
#define FULLM   0xffffffffu

__device__ double   g_contrib[BATCH];
__device__ double   g_cnt[BATCH];
__device__ unsigned g_sem = 0;

__device__ __forceinline__ float ex2f_(float x) { float r; asm("ex2.approx.f32 %0, %1;" : "=f"(r) : "f"(x)); return r; }
__device__ __forceinline__ unsigned long long pk2(float lo, float hi) {
    unsigned long long r; asm("mov.b64 %0, {%1, %2};" : "=l"(r) : "f"(lo), "f"(hi)); return r;
}
__device__ __forceinline__ void fma2(unsigned long long& d, unsigned long long a, unsigned long long b) {
    asm("fma.rn.f32x2 %0, %1, %2, %0;" : "+l"(d) : "l"(a), "l"(b));
}
__device__ __forceinline__ void add2(unsigned long long& d, unsigned long long a, unsigned long long b) {
    asm("add.rn.f32x2 %0, %1, %2;" : "=l"(d) : "l"(a), "l"(b));
}
__device__ __forceinline__ void upk(unsigned long long v, float& x, float& y) {
    asm("mov.b64 {%0, %1}, %2;" : "=f"(x), "=f"(y) : "l"(v));
}

// Probe mask dtype from its first bytes (mask[0]=mask[1]=true since len>=256).
__device__ __forceinline__ int probe_mask_mode(const void* m) {
    const unsigned char* u = (const unsigned char*)m;
    if (u[0] != 0 && u[1] != 0) return 0;           // u8 / bool
    if (u[0] == 0) return (u[3] != 0) ? 2 : 4;      // f32 : f64
    return (u[4] != 0) ? 1 : 3;                     // i32 : i64
}
__device__ __forceinline__ bool mask_at(const void* m, int mode, size_t k) {
    switch (mode) {
        case 0:  return ((const unsigned char*)m)[k] != 0;
        case 1:  return ((const int*)m)[k] != 0;
        case 2:  return ((const float*)m)[k] != 0.0f;
        default: { const int* p = (const int*)m; return (p[2*k] | p[2*k+1]) != 0; } // 64-bit
    }
}

// One recursion step: pcur' = (E-quarter-split matvec of warp's pcur) * ek * sc.
__device__ __forceinline__ void chain_step(
    float ek, float mk, int qbase,
    const unsigned long long* __restrict__ E2a,
    const unsigned long long* __restrict__ E2b,
    float& pcur, float& sc, int& Kacc, int& pend, float& EMs)
{
    float bb[8];
    #pragma unroll
    for (int i = 0; i < 8; i++) bb[i] = __shfl_sync(FULLM, pcur, qbase + i);

    unsigned long long ra0 = 0ull, ra1 = 0ull, rb0 = 0ull, rb1 = 0ull;
    #pragma unroll
    for (int i = 0; i < 8; i += 2) {
        unsigned long long bp0 = pk2(bb[i],     bb[i]);
        unsigned long long bp1 = pk2(bb[i + 1], bb[i + 1]);
        fma2(ra0, bp0, E2a[i]);     fma2(rb0, bp0, E2b[i]);
        fma2(ra1, bp1, E2a[i + 1]); fma2(rb1, bp1, E2b[i + 1]);
    }
    add2(ra0, ra0, ra1);
    add2(rb0, rb0, rb1);
    float r0, r1, r2, r3;
    upk(ra0, r0, r1);   // partials for columns (k, k^8)   over own t-quarter
    upk(rb0, r2, r3);   // partials for columns (k^16,k^24) over own t-quarter

    float a0  = r0 + __shfl_xor_sync(FULLM, r1, 8);
    float a2  = r2 + __shfl_xor_sync(FULLM, r3, 8);
    float acc = a0 + __shfl_xor_sync(FULLM, a2, 16);

    pcur = acc * (ek * sc);

    float p0 = __shfl_sync(FULLM, pcur, 0);
    int ee = __float_as_int(p0) >> 23;
    Kacc += pend; pend = ee - 127;
    sc = __int_as_float((254 - ee) << 23);
    EMs += mk;
}

// Run nsteps of the scaled recursion in direction DIR (+1 fwd, -1 bwd),
// with 2-group emission prefetch pipeline.
template<int DIR>
__device__ __forceinline__ void run_chain(
    const float* __restrict__ emb, int jstart, int nsteps, int lane, int qbase,
    const unsigned long long* __restrict__ E2a,
    const unsigned long long* __restrict__ E2b,
    float& pcur, float& sc, int& Kacc, int& pend, float& EMs)
{
    const float L2E = 1.4426950408889634f;
    float efA[4], efB[4], eA[4], mA[4];
    #pragma unroll
    for (int i = 0; i < 4; i++) {
        int j0 = jstart + DIR * i;
        j0 = (DIR > 0) ? min(j0, SLEN - 1) : max(j0, 0);
        efA[i] = emb[j0 * TT + lane];
    }
    #pragma unroll
    for (int i = 0; i < 4; i++) {
        int j0 = jstart + DIR * (4 + i);
        j0 = (DIR > 0) ? min(j0, SLEN - 1) : max(j0, 0);
        efB[i] = emb[j0 * TT + lane];
    }
    #pragma unroll
    for (int i = 0; i < 4; i++) {
        float t  = efA[i] * L2E;
        float t0 = __shfl_sync(FULLM, t, 0);
        eA[i] = ex2f_(t - t0); mA[i] = t0;
    }

    int j = jstart, done = 0;
    while (done + 4 <= nsteps) {
        float efN[4], eB[4], mB[4];
        #pragma unroll
        for (int i = 0; i < 4; i++) {
            int j0 = j + DIR * (8 + i);
            j0 = (DIR > 0) ? min(j0, SLEN - 1) : max(j0, 0);
            efN[i] = emb[j0 * TT + lane];
        }
        #pragma unroll
        for (int i = 0; i < 4; i++) {
            float t  = efB[i] * L2E;
            float t0 = __shfl_sync(FULLM, t, 0);
            eB[i] = ex2f_(t - t0); mB[i] = t0;
        }
        #pragma unroll
        for (int k = 0; k < 4; k++)
            chain_step(eA[k], mA[k], qbase, E2a, E2b, pcur, sc, Kacc, pend, EMs);
        #pragma unroll
        for (int i = 0; i < 4; i++) { eA[i] = eB[i]; mA[i] = mB[i]; efB[i] = efN[i]; }
        j += DIR * 4; done += 4;
    }
    #pragma unroll
    for (int k = 0; k < 4; k++) {
        if (done < nsteps) {
            chain_step(eA[k], mA[k], qbase, E2a, E2b, pcur, sc, Kacc, pend, EMs);
            done++;
        }
    }
}

__global__ void __launch_bounds__(THREADS)
crf_fused_kernel(const float* __restrict__ em,
                 const int* __restrict__ tags,
                 const void* __restrict__ maskp,
                 const float* __restrict__ startv,
                 const float* __restrict__ transv,
                 const float* __restrict__ endv,
                 float* __restrict__ out)
{
    __shared__ float s_trans[TT * TT];
    __shared__ float s_start[TT];
    __shared__ float s_end[TT];
    __shared__ __align__(16) float s_bm[BPB][TT];   // B_mid from backward warp
    __shared__ double s_nb[BPB];                    // backward numerator partial
    __shared__ double s_cb[BPB];                    // backward log2 constant
    __shared__ double s_r1[NWARP], s_r2[NWARP];
    __shared__ bool   s_last;

    const int  tid   = threadIdx.x;
    const int  w     = tid >> 5;
    const int  lane  = tid & 31;
    const bool isF   = (w < BPB);
    const int  slot  = isF ? w : (w - BPB);
    const int  b     = blockIdx.x * BPB + slot;
    const int  qbase = (lane >> 3) << 3;

    for (int i = tid; i < TT * TT; i += THREADS) s_trans[i] = transv[i];
    if (tid < TT) { s_start[tid] = startv[tid]; s_end[tid] = endv[tid]; }
    __syncthreads();

    const float L2E = 1.4426950408889634f;

    int head = 0, tail = -1, len = 0;
    if (b < BATCH) {
        const int mmode = probe_mask_mode(maskp);
        const size_t mbase = (size_t)b * SLEN;
        int h = -1;
        #pragma unroll 4
        for (int i = 0; i < SLEN / 32; i++) {
            bool mv = mask_at(maskp, mmode, mbase + i * 32 + lane);
            unsigned bits = __ballot_sync(FULLM, mv);
            len += __popc(bits);
            if (bits) {
                if (h < 0) h = i * 32 + (__ffs(bits) - 1);
                tail = i * 32 + 31 - __clz(bits);
            }
        }
        head = (h < 0) ? 0 : h;
    }

    const bool active = (b < BATCH) && (len > 0);
    float  pcurF = 0.0f, c20 = 0.0f, EMsF = 0.0f;
    int    KaccF = 0;
    double nsumF = 0.0;
    int    mid = 0;

    if (active) {
        const float* emb = em + (size_t)b * SLEN * TT;
        const int*   tg  = tags + (size_t)b * SLEN;
        mid = (head + tail) >> 1;

        if (isF) {
            // ---------- FORWARD WARP ----------
            double nsum = 0.0;
            #pragma unroll 4
            for (int j = head + 1 + lane; j <= mid; j += 32) {
                int tj = tg[j], tp = tg[j - 1];
                nsum += (double)s_trans[tp * TT + tj] + (double)emb[j * TT + tj];
            }
            #pragma unroll
            for (int o = 16; o; o >>= 1) nsum += __shfl_xor_sync(FULLM, nsum, o);
            int th = tg[head], tl = tg[tail];
            nsumF = nsum + (double)s_start[th] + (double)emb[head * TT + th] + (double)s_end[tl];

            // E columns split per lane: quarter t = qbase..qbase+7, cols {k,k^8,k^16,k^24}
            unsigned long long E2a[8], E2b[8];
            #pragma unroll
            for (int i = 0; i < 8; i++) {
                int t = qbase + i;
                E2a[i] = pk2(expf(s_trans[t * TT + lane]),
                             expf(s_trans[t * TT + (lane ^ 8)]));
                E2b[i] = pk2(expf(s_trans[t * TT + (lane ^ 16)]),
                             expf(s_trans[t * TT + (lane ^ 24)]));
            }

            float s2 = (s_start[lane] + emb[head * TT + lane]) * L2E;
            c20 = __shfl_sync(FULLM, s2, 0);
            pcurF = exp2f(s2 - c20);

            float sc = 1.0f; int pend = 0;
            run_chain<1>(emb, head + 1, mid - head, lane, qbase, E2a, E2b,
                         pcurF, sc, KaccF, pend, EMsF);
            // last pend intentionally dropped (its sc never applied)
        } else {
            // ---------- BACKWARD WARP ----------
            double nsum = 0.0;
            #pragma unroll 4
            for (int j = mid + 1 + lane; j <= tail; j += 32) {
                int tj = tg[j], tp = tg[j - 1];
                nsum += (double)s_trans[tp * TT + tj] + (double)emb[j * TT + tj];
            }
            #pragma unroll
            for (int o = 16; o; o >>= 1) nsum += __shfl_xor_sync(FULLM, nsum, o);
            if (lane == 0) s_nb[slot] = nsum;

            // E^T split: E'[t][c] = exp(trans[c][t])
            unsigned long long E2a[8], E2b[8];
            #pragma unroll
            for (int i = 0; i < 8; i++) {
                int t = qbase + i;
                E2a[i] = pk2(expf(s_trans[lane * TT + t]),
                             expf(s_trans[(lane ^ 8) * TT + t]));
                E2b[i] = pk2(expf(s_trans[(lane ^ 16) * TT + t]),
                             expf(s_trans[(lane ^ 24) * TT + t]));
            }

            float em2t = emb[tail * TT + lane] * L2E;
            float t0i  = __shfl_sync(FULLM, em2t, 0);
            float pcur = exp2f(em2t - t0i) * expf(s_end[lane]);
            float EMs  = t0i;
            float v0n  = __shfl_sync(FULLM, pcur, 0);
            int   e0   = __float_as_int(v0n) >> 23;
            int Kacc = 0, pend = e0 - 127;
            float sc = __int_as_float((254 - e0) << 23);

            run_chain<-1>(emb, tail - 1, tail - mid - 1, lane, qbase, E2a, E2b,
                          pcur, sc, Kacc, pend, EMs);

            // final dot (no emission): B_mid = E' * v_{mid+1}, apply pending sc
            {
                float bb[8];
                #pragma unroll
                for (int i = 0; i < 8; i++) bb[i] = __shfl_sync(FULLM, pcur, qbase + i);
                unsigned long long ra0 = 0ull, ra1 = 0ull, rb0 = 0ull, rb1 = 0ull;
                #pragma unroll
                for (int i = 0; i < 8; i += 2) {
                    unsigned long long bp0 = pk2(bb[i],     bb[i]);
                    unsigned long long bp1 = pk2(bb[i + 1], bb[i + 1]);
                    fma2(ra0, bp0, E2a[i]);     fma2(rb0, bp0, E2b[i]);
                    fma2(ra1, bp1, E2a[i + 1]); fma2(rb1, bp1, E2b[i + 1]);
                }
                add2(ra0, ra0, ra1); add2(rb0, rb0, rb1);
                float r0, r1, r2, r3; upk(ra0, r0, r1); upk(rb0, r2, r3);
                float a0  = r0 + __shfl_xor_sync(FULLM, r1, 8);
                float a2  = r2 + __shfl_xor_sync(FULLM, r3, 8);
                float acc = a0 + __shfl_xor_sync(FULLM, a2, 16);
                float bm  = acc * sc;
                Kacc += pend;
                s_bm[slot][lane] = bm;
                if (lane == 0) s_cb[slot] = (double)EMs + (double)Kacc;
            }
        }
    }

    __syncthreads();   // backward results (s_bm, s_nb, s_cb) visible

    if (b < BATCH && isF) {
        if (active) {
            float vv = pcurF * s_bm[slot][lane];
            #pragma unroll
            for (int o = 16; o; o >>= 1) vv += __shfl_xor_sync(FULLM, vv, o);
            const double LN2 = 0.6931471805599453;
            double denom = ((double)c20 + (double)EMsF + (double)KaccF
                            + s_cb[slot] + (double)log2f(vv)) * LN2;
            double num = nsumF + s_nb[slot];
            if (lane == 0) {
                g_contrib[b] = (denom - num) / ((double)len + 1e-6);
                g_cnt[b]     = 1.0;
            }
        } else if (lane == 0) {
            g_contrib[b] = 0.0; g_cnt[b] = 0.0;
        }
    }

    // ---- last-block-done fused reduction (deterministic fixed order) ----
    __syncthreads();
    if (tid == 0) {
        __threadfence();
        s_last = (atomicAdd(&g_sem, 1u) == (unsigned)(gridDim.x - 1));
    }
    __syncthreads();
    if (s_last) {
        __threadfence();
        double a = 0.0, c = 0.0;
        for (int i = tid; i < BATCH; i += THREADS) { a += g_contrib[i]; c += g_cnt[i]; }
        #pragma unroll
        for (int o = 16; o; o >>= 1) {
            a += __shfl_xor_sync(FULLM, a, o);
            c += __shfl_xor_sync(FULLM, c, o);
        }
        if (lane == 0) { s_r1[w] = a; s_r2[w] = c; }
        __syncthreads();
        if (tid == 0) {
            double A = 0.0, C = 0.0;
            for (int i = 0; i < NWARP; i++) { A += s_r1[i]; C += s_r2[i]; }
            out[0] = (float)(A / (C + 1e-6));
            g_sem = 0;   // re-arm for next graph replay
        }
    }
}

extern "C" void kernel_launch(void* const* d_in, const int* in_sizes, int n_in,
                              void* d_out, int out_size)
{
    const float* em    = (const float*)d_in[0];
    const int*   tags  = (const int*)d_in[1];
    const void*  mask  = (const void*)d_in[2];
    const float* st    = (const float*)d_in[3];
    const float* tr    = (const float*)d_in[4];
    const float* en    = (const float*)d_in[5];

    crf_fused_kernel<<<NBLK, THREADS>>>(em, tags, mask, st, tr, en, (float*)d_out);
}